// round 2
// baseline (speedup 1.0000x reference)
#include <cuda_runtime.h>
#include <cuda_bf16.h>

__device__ float g_x3[4*3*256*256];
__device__ float g_x6[4*3*256*256];
__device__ float g_x9[4*3*256*256];
__device__ float g_xg[4];

__device__ __forceinline__ int reflect256(int t) {
    t = (t < 0) ? -t : t;
    return (t >= 256) ? (510 - t) : t;
}

// per-batch max of x (the reference softmax over a singleton axis == 1)
__global__ __launch_bounds__(256) void max_kernel(const float* __restrict__ X) {
    int b = blockIdx.x;
    const float* xb = X + b*3*65536;
    float m = -1e30f;
    for (int i = threadIdx.x; i < 3*65536; i += 256)
        m = fmaxf(m, xb[i]);
    __shared__ float sm[8];
    #pragma unroll
    for (int o = 16; o > 0; o >>= 1) m = fmaxf(m, __shfl_xor_sync(0xffffffffu, m, o));
    if ((threadIdx.x & 31) == 0) sm[threadIdx.x >> 5] = m;
    __syncthreads();
    if (threadIdx.x < 32) {
        float v = (threadIdx.x < 8) ? sm[threadIdx.x] : -1e30f;
        #pragma unroll
        for (int o = 4; o > 0; o >>= 1) v = fmaxf(v, __shfl_xor_sync(0xffffffffu, v, o));
        if (threadIdx.x == 0) g_xg[b] = v;
    }
}

// stage 1: p=1, nh=6, bias==1. one thread per window, neighborhood in regs.
__global__ __launch_bounds__(256) void attn1_kernel(
    const float* __restrict__ X, const float* __restrict__ W,
    const float* __restrict__ B, const float* __restrict__ HW)
{
    int n = blockIdx.x*256 + threadIdx.x;
    int j = n & 255, i = (n >> 8) & 255, b = n >> 16;

    float xn[9][3];
    #pragma unroll
    for (int k = 0; k < 9; k++) {
        int yy = reflect256(i + k/3 - 1);
        int xx = reflect256(j + k%3 - 1);
        const float* p = X + b*3*65536 + yy*256 + xx;
        #pragma unroll
        for (int c = 0; c < 3; c++) xn[k][c] = p[c*65536];
    }

    const float rs = 0.5773502691896258f; // 1/sqrt(3)
    float res[3] = {0.f, 0.f, 0.f};

    #pragma unroll 1
    for (int h = 0; h < 6; h++) {
        float hw = __ldg(HW + h);
        #pragma unroll
        for (int c = 0; c < 3; c++) {
            int mq = (h*3+0)*3 + c, mk = (h*3+1)*3 + c, mv = (h*3+2)*3 + c;
            float q = __ldg(B+mq) + __ldg(W+mq*3+0)*xn[4][0]
                                  + __ldg(W+mq*3+1)*xn[4][1]
                                  + __ldg(W+mq*3+2)*xn[4][2];
            q *= rs;
            float wk0=__ldg(W+mk*3+0), wk1=__ldg(W+mk*3+1), wk2=__ldg(W+mk*3+2), bk=__ldg(B+mk);
            float sc[9], mx = -1e30f;
            #pragma unroll
            for (int k = 0; k < 9; k++) {
                float kv = bk + wk0*xn[k][0] + wk1*xn[k][1] + wk2*xn[k][2];
                sc[k] = q * kv;
                mx = fmaxf(mx, sc[k]);
            }
            float sum = 0.f;
            #pragma unroll
            for (int k = 0; k < 9; k++) { sc[k] = __expf(sc[k] - mx); sum += sc[k]; }
            float wv0=__ldg(W+mv*3+0), wv1=__ldg(W+mv*3+1), wv2=__ldg(W+mv*3+2), bv=__ldg(B+mv);
            float o = 0.f;
            #pragma unroll
            for (int k = 0; k < 9; k++) {
                float vv = bv + wv0*xn[k][0] + wv1*xn[k][1] + wv2*xn[k][2];
                o += sc[k]*vv;
            }
            res[c] += hw * o / sum;
        }
    }
    #pragma unroll
    for (int c = 0; c < 3; c++)
        g_x3[(b*3+c)*65536 + i*256 + j] = res[c];
}

// stages 2/3: thread = (window, head, c_out)
template<int P, int NH, int WPB>
__global__ __launch_bounds__(WPB*NH*3) void attn_kernel(
    const float* __restrict__ W, const float* __restrict__ B, const float* __restrict__ HW)
{
    constexpr int PP = P*P, L = 3*PP, HC = NH*3, M = NH*3*L;
    constexpr int NHW  = (P==2) ? 128 : 86;
    constexpr int NWIN = 4*NHW*NHW;
    constexpr int PADH = (P==2) ? 0 : 2;
    constexpr int PADL = P + PADH;
    constexpr int CH   = (P==2) ? 4 : 3;
    constexpr int XS   = 9*L;
    constexpr float RS = (P==2) ? 0.2886751345948129f : 0.1924500897298753f; // 1/sqrt(L)

    __shared__ float sx[WPB*XS];
    __shared__ float sw[M*L];

    const float* Xg = (P==2) ? g_x3 : g_x6;
    float*       Og = (P==2) ? g_x6 : g_x9;

    const int tid = threadIdx.x;
    constexpr int NTH = WPB*HC;

    for (int idx = tid; idx < M*L; idx += NTH) sw[idx] = W[idx];

    const int n0 = blockIdx.x * WPB;
    for (int idx = tid; idx < WPB*XS; idx += NTH) {
        int wl = idx / XS, rem = idx % XS;
        int n = n0 + wl;
        float v = 0.f;
        if (n < NWIN) {
            int wj = n % NHW, wi = (n / NHW) % NHW, b = n / (NHW*NHW);
            int k9 = rem / L, l = rem % L;
            int c = l / PP, rr = (l % PP) / P, ss = l % P;
            int y  = reflect256((wi + k9/3)*P + rr - PADL);
            int x2 = reflect256((wj + k9%3)*P + ss - PADL);
            v = Xg[(b*3+c)*65536 + y*256 + x2];
        }
        sx[idx] = v;
    }
    __syncthreads();

    const int hc = tid % HC, wl = tid / HC;
    const int h = hc % NH, c = hc / NH;
    const int n = n0 + wl;
    const bool active = (n < NWIN);
    const int wj = n % NHW, wi = (n / NHW) % NHW, b = n / (NHW*NHW);
    const float* xw = sx + wl*XS;

    float etab[2*P-1];
    #pragma unroll
    for (int t = 0; t < 2*P-1; t++) etab[t] = __expf(-(float)t / (float)P);

    const int mqb = ((h*3+0)*3 + c)*PP;
    const int mkb = ((h*3+1)*3 + c)*PP;
    const int mvb = ((h*3+2)*3 + c)*PP;

    // q (center neighbor only)
    float q[PP];
    #pragma unroll
    for (int pos = 0; pos < PP; pos++) q[pos] = __ldg(B + mqb + pos);
    #pragma unroll
    for (int l = 0; l < L; l++) {
        float xv = xw[4*L + l];
        #pragma unroll
        for (int pos = 0; pos < PP; pos++)
            q[pos] += xv * sw[(mqb+pos)*L + l];
    }
    #pragma unroll
    for (int pos = 0; pos < PP; pos++) q[pos] *= RS;

    // k pass -> scores (bias folded in)
    float score[9];
    #pragma unroll
    for (int k = 0; k < 9; k++) score[k] = 0.f;

    float wreg[CH*L];
    #pragma unroll
    for (int pc = 0; pc < PP; pc += CH) {
        #pragma unroll
        for (int i2 = 0; i2 < CH*L; i2++) wreg[i2] = sw[(mkb+pc)*L + i2];
        float bk[CH];
        #pragma unroll
        for (int cc = 0; cc < CH; cc++) bk[cc] = __ldg(B + mkb + pc + cc);
        #pragma unroll
        for (int k = 0; k < 9; k++) {
            float acc[CH];
            #pragma unroll
            for (int cc = 0; cc < CH; cc++) acc[cc] = bk[cc];
            #pragma unroll
            for (int l = 0; l < L; l++) {
                float xv = xw[k*L + l];
                #pragma unroll
                for (int cc = 0; cc < CH; cc++) acc[cc] += xv * wreg[cc*L + l];
            }
            #pragma unroll
            for (int cc = 0; cc < CH; cc++) {
                const int pos = pc + cc;
                const int ii = pos / P, jj = pos % P;
                const int di = k / 3, dj = k % 3;
                const int u  = (di==0) ? (P-1-ii) : ((di==1) ? 0 : ii);
                const int v2 = (dj==0) ? (P-1-jj) : ((dj==1) ? 0 : jj);
                score[k] += q[pos] * acc[cc] * etab[u+v2];
            }
        }
    }

    // softmax over the 9 neighbors
    float mx = score[0];
    #pragma unroll
    for (int k = 1; k < 9; k++) mx = fmaxf(mx, score[k]);
    float sum = 0.f;
    #pragma unroll
    for (int k = 0; k < 9; k++) { score[k] = __expf(score[k]-mx); sum += score[k]; }
    float inv = 1.f / sum;

    // v pass -> out
    float outv[PP];
    #pragma unroll
    for (int pos = 0; pos < PP; pos++) outv[pos] = 0.f;
    #pragma unroll
    for (int pc = 0; pc < PP; pc += CH) {
        #pragma unroll
        for (int i2 = 0; i2 < CH*L; i2++) wreg[i2] = sw[(mvb+pc)*L + i2];
        float bv[CH];
        #pragma unroll
        for (int cc = 0; cc < CH; cc++) bv[cc] = __ldg(B + mvb + pc + cc);
        #pragma unroll
        for (int k = 0; k < 9; k++) {
            float acc[CH];
            #pragma unroll
            for (int cc = 0; cc < CH; cc++) acc[cc] = bv[cc];
            #pragma unroll
            for (int l = 0; l < L; l++) {
                float xv = xw[k*L + l];
                #pragma unroll
                for (int cc = 0; cc < CH; cc++) acc[cc] += xv * wreg[cc*L + l];
            }
            #pragma unroll
            for (int cc = 0; cc < CH; cc++) outv[pc+cc] += score[k] * acc[cc];
        }
    }
    const float hwv = __ldg(HW + h) * inv;
    #pragma unroll
    for (int pos = 0; pos < PP; pos++) outv[pos] *= hwv;

    // head reduction: NH adjacent lanes, group start aligned to NH (HC%4==0 cases hold)
    #pragma unroll
    for (int pos = 0; pos < PP; pos++) {
        outv[pos] += __shfl_xor_sync(0xffffffffu, outv[pos], 1);
        if (NH == 4) outv[pos] += __shfl_xor_sync(0xffffffffu, outv[pos], 2);
    }

    if (h == 0 && active) {
        #pragma unroll
        for (int pos = 0; pos < PP; pos++) {
            int y  = wi*P + pos/P - PADH;
            int x2 = wj*P + pos%P - PADH;
            if (y >= 0 && x2 >= 0)
                Og[(b*3+c)*65536 + y*256 + x2] = outv[pos];
        }
    }
}

// 5x5 conv (9->3 channels) fused with the final elementwise gate
__global__ __launch_bounds__(128) void conv_final_kernel(
    const float* __restrict__ X, const float* __restrict__ CW,
    const float* __restrict__ CB, float* __restrict__ out)
{
    __shared__ float sx[9][20][37];
    __shared__ float sw[675];
    __shared__ float sb[3];
    const int b = blockIdx.z;
    const int x0 = blockIdx.x * 32, y0 = blockIdx.y * 16;
    const int tid = threadIdx.x;

    for (int i2 = tid; i2 < 675; i2 += 128) sw[i2] = CW[i2];
    if (tid < 3) sb[tid] = CB[tid];
    for (int i2 = tid; i2 < 9*20*36; i2 += 128) {
        int ci = i2 / 720, rem = i2 % 720, yy = rem / 36, xx = rem % 36;
        int gy = y0 + yy - 2, gx = x0 + xx - 2;
        float v = 0.f;
        if ((unsigned)gy < 256u && (unsigned)gx < 256u) {
            const float* src = (ci < 3) ? g_x9 : ((ci < 6) ? g_x6 : g_x3);
            v = src[(b*3 + (ci % 3))*65536 + gy*256 + gx];
        }
        sx[ci][yy][xx] = v;
    }
    __syncthreads();

    const int tx = tid & 15, ty = tid >> 4;
    const int lx = tx*2, ly = ty*2;
    float acc[3][4];
    #pragma unroll
    for (int c2 = 0; c2 < 3; c2++)
        #pragma unroll
        for (int p2 = 0; p2 < 4; p2++) acc[c2][p2] = 0.f;

    #pragma unroll 1
    for (int ci = 0; ci < 9; ci++) {
        #pragma unroll
        for (int ky = 0; ky < 5; ky++) {
            #pragma unroll
            for (int kx = 0; kx < 5; kx++) {
                float w0 = sw[      ci*25 + ky*5 + kx];
                float w1 = sw[225 + ci*25 + ky*5 + kx];
                float w2 = sw[450 + ci*25 + ky*5 + kx];
                float a00 = sx[ci][ly+ky  ][lx+kx  ];
                float a01 = sx[ci][ly+ky  ][lx+kx+1];
                float a10 = sx[ci][ly+ky+1][lx+kx  ];
                float a11 = sx[ci][ly+ky+1][lx+kx+1];
                acc[0][0] += w0*a00; acc[0][1] += w0*a01; acc[0][2] += w0*a10; acc[0][3] += w0*a11;
                acc[1][0] += w1*a00; acc[1][1] += w1*a01; acc[1][2] += w1*a10; acc[1][3] += w1*a11;
                acc[2][0] += w2*a00; acc[2][1] += w2*a01; acc[2][2] += w2*a10; acc[2][3] += w2*a11;
            }
        }
    }

    const float xg = g_xg[b];
    #pragma unroll
    for (int co = 0; co < 3; co++) {
        #pragma unroll
        for (int py = 0; py < 2; py++) {
            #pragma unroll
            for (int px = 0; px < 2; px++) {
                int gy = y0 + ly + py, gx = x0 + lx + px;
                float x0v = fmaxf(acc[co][py*2+px] + sb[co], 0.f);
                float xv = X[(b*3+co)*65536 + gy*256 + gx];
                float r = fmaxf(xv * x0v + xg - x0v, 0.f);
                out[(b*3+co)*65536 + gy*256 + gx] = r;
            }
        }
    }
}

extern "C" void kernel_launch(void* const* d_in, const int* in_sizes, int n_in,
                              void* d_out, int out_size) {
    (void)in_sizes; (void)n_in; (void)out_size;
    const float* x   = (const float*)d_in[0];
    const float* w3  = (const float*)d_in[1];
    const float* b3  = (const float*)d_in[2];
    const float* hw3 = (const float*)d_in[3];
    const float* w6  = (const float*)d_in[4];
    const float* b6  = (const float*)d_in[5];
    const float* hw6 = (const float*)d_in[6];
    const float* w9  = (const float*)d_in[7];
    const float* b9  = (const float*)d_in[8];
    const float* hw9 = (const float*)d_in[9];
    const float* cw  = (const float*)d_in[10];
    const float* cb  = (const float*)d_in[11];
    float* out = (float*)d_out;

    max_kernel<<<4, 256>>>(x);
    attn1_kernel<<<1024, 256>>>(x, w3, b3, hw3);

    // stage 2: P=2, NH=4, WPB=16 -> 192 threads, 65536 windows
    attn_kernel<2, 4, 16><<<(65536 + 15) / 16, 16 * 12>>>(w6, b6, hw6);

    // stage 3: P=3, NH=2, WPB=16 -> 96 threads, 29584 windows
    attn_kernel<3, 2, 16><<<(29584 + 15) / 16, 16 * 6>>>(w9, b9, hw9);

    conv_final_kernel<<<dim3(8, 16, 4), 128>>>(x, cw, cb, out);
}

// round 3
// speedup vs baseline: 1.4198x; 1.4198x over previous
#include <cuda_runtime.h>
#include <cuda_bf16.h>

__device__ float g_x3[4*3*256*256];
__device__ float g_x6[4*3*256*256];
__device__ float g_x9[4*3*256*256];
__device__ float g_xg[4];

__device__ __forceinline__ int reflect256(int t) {
    t = (t < 0) ? -t : t;
    return (t >= 256) ? (510 - t) : t;
}

// exp(-t/P) as compile-time literals
template<int P>
__device__ __forceinline__ constexpr float ebias(int t) {
    return (t == 0) ? 1.0f
         : (t == 1) ? ((P == 2) ? 0.60653065971263342f : 0.71653131057378927f)
         : 0.51341711903259202f; // t==2 only occurs for P==3
}

// per-batch max of x (the reference softmax over a singleton axis == 1)
__global__ __launch_bounds__(256) void max_kernel(const float* __restrict__ X) {
    int b = blockIdx.x;
    const float* xb = X + b*3*65536;
    float m = -1e30f;
    for (int i = threadIdx.x; i < 3*65536; i += 256)
        m = fmaxf(m, xb[i]);
    __shared__ float sm[8];
    #pragma unroll
    for (int o = 16; o > 0; o >>= 1) m = fmaxf(m, __shfl_xor_sync(0xffffffffu, m, o));
    if ((threadIdx.x & 31) == 0) sm[threadIdx.x >> 5] = m;
    __syncthreads();
    if (threadIdx.x < 32) {
        float v = (threadIdx.x < 8) ? sm[threadIdx.x] : -1e30f;
        #pragma unroll
        for (int o = 4; o > 0; o >>= 1) v = fmaxf(v, __shfl_xor_sync(0xffffffffu, v, o));
        if (threadIdx.x == 0) g_xg[b] = v;
    }
}

// stage 1: p=1, nh=6, bias==1. one thread per window, neighborhood in regs.
__global__ __launch_bounds__(256) void attn1_kernel(
    const float* __restrict__ X, const float* __restrict__ W,
    const float* __restrict__ B, const float* __restrict__ HW)
{
    int n = blockIdx.x*256 + threadIdx.x;
    int j = n & 255, i = (n >> 8) & 255, b = n >> 16;

    float xn[9][3];
    #pragma unroll
    for (int k = 0; k < 9; k++) {
        int yy = reflect256(i + k/3 - 1);
        int xx = reflect256(j + k%3 - 1);
        const float* p = X + b*3*65536 + yy*256 + xx;
        #pragma unroll
        for (int c = 0; c < 3; c++) xn[k][c] = p[c*65536];
    }

    const float rs = 0.5773502691896258f; // 1/sqrt(3)
    float res[3] = {0.f, 0.f, 0.f};

    #pragma unroll 1
    for (int h = 0; h < 6; h++) {
        float hw = __ldg(HW + h);
        #pragma unroll
        for (int c = 0; c < 3; c++) {
            int mq = (h*3+0)*3 + c, mk = (h*3+1)*3 + c, mv = (h*3+2)*3 + c;
            float q = __ldg(B+mq) + __ldg(W+mq*3+0)*xn[4][0]
                                  + __ldg(W+mq*3+1)*xn[4][1]
                                  + __ldg(W+mq*3+2)*xn[4][2];
            q *= rs;
            float wk0=__ldg(W+mk*3+0), wk1=__ldg(W+mk*3+1), wk2=__ldg(W+mk*3+2), bk=__ldg(B+mk);
            float sc[9], mx = -1e30f;
            #pragma unroll
            for (int k = 0; k < 9; k++) {
                float kv = bk + wk0*xn[k][0] + wk1*xn[k][1] + wk2*xn[k][2];
                sc[k] = q * kv;
                mx = fmaxf(mx, sc[k]);
            }
            float sum = 0.f;
            #pragma unroll
            for (int k = 0; k < 9; k++) { sc[k] = __expf(sc[k] - mx); sum += sc[k]; }
            float wv0=__ldg(W+mv*3+0), wv1=__ldg(W+mv*3+1), wv2=__ldg(W+mv*3+2), bv=__ldg(B+mv);
            float o = 0.f;
            #pragma unroll
            for (int k = 0; k < 9; k++) {
                float vv = bv + wv0*xn[k][0] + wv1*xn[k][1] + wv2*xn[k][2];
                o += sc[k]*vv;
            }
            res[c] += hw * o / sum;
        }
    }
    #pragma unroll
    for (int c = 0; c < 3; c++)
        g_x3[(b*3+c)*65536 + i*256 + j] = res[c];
}

// stages 2/3: thread = (window, head, c_out); row-chunked (one live wreg generation)
template<int P, int NH, int WPB>
__global__ __launch_bounds__(WPB*NH*3, 4) void attn_kernel(
    const float* __restrict__ W, const float* __restrict__ B, const float* __restrict__ HW)
{
    constexpr int PP = P*P, L = 3*PP, HC = NH*3, M = NH*3*L;
    constexpr int NHW  = (P==2) ? 128 : 86;
    constexpr int NWIN = 4*NHW*NHW;
    constexpr int PADH = (P==2) ? 0 : 2;
    constexpr int PADL = P + PADH;
    constexpr int XS   = 9*L;
    constexpr float RS = (P==2) ? 0.2886751345948129f : 0.1924500897298753f; // 1/sqrt(L)

    __shared__ float sx[WPB*XS];
    __shared__ float sw[M*L];

    const float* Xg = (P==2) ? g_x3 : g_x6;
    float*       Og = (P==2) ? g_x6 : g_x9;

    const int tid = threadIdx.x;
    constexpr int NTH = WPB*HC;

    for (int idx = tid; idx < M*L; idx += NTH) sw[idx] = W[idx];

    const int n0 = blockIdx.x * WPB;
    for (int idx = tid; idx < WPB*XS; idx += NTH) {
        int wl = idx / XS, rem = idx % XS;
        int n = n0 + wl;
        float v = 0.f;
        if (n < NWIN) {
            int wj = n % NHW, wi = (n / NHW) % NHW, b = n / (NHW*NHW);
            int k9 = rem / L, l = rem % L;
            int c = l / PP, rr = (l % PP) / P, ss = l % P;
            int y  = reflect256((wi + k9/3)*P + rr - PADL);
            int x2 = reflect256((wj + k9%3)*P + ss - PADL);
            v = Xg[(b*3+c)*65536 + y*256 + x2];
        }
        sx[idx] = v;
    }
    __syncthreads();

    const int hc = tid % HC, wl = tid / HC;
    const int h = hc % NH, c = hc / NH;
    const int n = n0 + wl;
    const bool active = (n < NWIN);
    const int wj = n % NHW, wi = (n / NHW) % NHW, b = n / (NHW*NHW);
    const float* xw = sx + wl*XS;

    const int mqb = ((h*3+0)*3 + c)*PP;
    const int mkb = ((h*3+1)*3 + c)*PP;
    const int mvb = ((h*3+2)*3 + c)*PP;

    float score[9];
    #pragma unroll
    for (int k = 0; k < 9; k++) score[k] = 0.f;

    float wreg[P*L];

    // ---- k pass, one row of positions at a time ----
    #pragma unroll 1
    for (int ii = 0; ii < P; ii++) {
        const int rowq = mqb + ii*P;
        const int rowk = mkb + ii*P;

        // q for this row
        float qr[P];
        #pragma unroll
        for (int jj = 0; jj < P; jj++) qr[jj] = __ldg(B + rowq + jj);
        #pragma unroll
        for (int jj = 0; jj < P; jj++)
            #pragma unroll
            for (int l = 0; l < L; l++) wreg[jj*L + l] = sw[(rowq+jj)*L + l];
        #pragma unroll
        for (int l = 0; l < L; l++) {
            float xv = xw[4*L + l];
            #pragma unroll
            for (int jj = 0; jj < P; jj++) qr[jj] += xv * wreg[jj*L + l];
        }
        #pragma unroll
        for (int jj = 0; jj < P; jj++) qr[jj] *= RS;

        // eu[di] = exp(-u/P): u = P-1-ii (di=0), 0 (di=1), ii (di=2)   [ii runtime]
        float eu0, eu2;
        if (P == 2) {
            eu0 = (ii == 0) ? ebias<P>(1) : ebias<P>(0);
            eu2 = (ii == 0) ? ebias<P>(0) : ebias<P>(1);
        } else {
            eu0 = (ii == 0) ? ebias<P>(2) : ((ii == 1) ? ebias<P>(1) : ebias<P>(0));
            eu2 = (ii == 0) ? ebias<P>(0) : ((ii == 1) ? ebias<P>(1) : ebias<P>(2));
        }
        float qe[3][P];
        #pragma unroll
        for (int jj = 0; jj < P; jj++) {
            qe[0][jj] = qr[jj]*eu0; qe[1][jj] = qr[jj]; qe[2][jj] = qr[jj]*eu2;
        }

        // k weights for this row
        float bk[P];
        #pragma unroll
        for (int jj = 0; jj < P; jj++) bk[jj] = __ldg(B + rowk + jj);
        #pragma unroll
        for (int jj = 0; jj < P; jj++)
            #pragma unroll
            for (int l = 0; l < L; l++) wreg[jj*L + l] = sw[(rowk+jj)*L + l];

        #pragma unroll
        for (int k = 0; k < 9; k++) {
            const int di = k/3, dj = k%3;
            float acc[P];
            #pragma unroll
            for (int jj = 0; jj < P; jj++) acc[jj] = bk[jj];
            #pragma unroll
            for (int l = 0; l < L; l++) {
                float xv = xw[k*L + l];
                #pragma unroll
                for (int jj = 0; jj < P; jj++) acc[jj] += xv * wreg[jj*L + l];
            }
            #pragma unroll
            for (int jj = 0; jj < P; jj++) {
                const float ev = (dj==0) ? ebias<P>(P-1-jj) : ((dj==1) ? 1.f : ebias<P>(jj));
                score[k] += qe[di][jj] * (ev * acc[jj]);
            }
        }
    }

    // softmax over the 9 neighbors
    float mx = score[0];
    #pragma unroll
    for (int k = 1; k < 9; k++) mx = fmaxf(mx, score[k]);
    float sum = 0.f;
    #pragma unroll
    for (int k = 0; k < 9; k++) { score[k] = __expf(score[k]-mx); sum += score[k]; }
    const float hwv = __ldg(HW + h) / sum;

    // ---- v pass, row at a time; reduce + store per row ----
    #pragma unroll 1
    for (int ii = 0; ii < P; ii++) {
        const int rowv = mvb + ii*P;
        float bv[P];
        #pragma unroll
        for (int jj = 0; jj < P; jj++) bv[jj] = __ldg(B + rowv + jj);
        #pragma unroll
        for (int jj = 0; jj < P; jj++)
            #pragma unroll
            for (int l = 0; l < L; l++) wreg[jj*L + l] = sw[(rowv+jj)*L + l];

        float outr[P];
        #pragma unroll
        for (int jj = 0; jj < P; jj++) outr[jj] = 0.f;
        #pragma unroll
        for (int k = 0; k < 9; k++) {
            float acc[P];
            #pragma unroll
            for (int jj = 0; jj < P; jj++) acc[jj] = bv[jj];
            #pragma unroll
            for (int l = 0; l < L; l++) {
                float xv = xw[k*L + l];
                #pragma unroll
                for (int jj = 0; jj < P; jj++) acc[jj] += xv * wreg[jj*L + l];
            }
            #pragma unroll
            for (int jj = 0; jj < P; jj++) outr[jj] += score[k] * acc[jj];
        }
        #pragma unroll
        for (int jj = 0; jj < P; jj++) outr[jj] *= hwv;

        // head reduction: NH adjacent lanes, aligned groups
        #pragma unroll
        for (int jj = 0; jj < P; jj++) {
            outr[jj] += __shfl_xor_sync(0xffffffffu, outr[jj], 1);
            if (NH == 4) outr[jj] += __shfl_xor_sync(0xffffffffu, outr[jj], 2);
        }

        if (h == 0 && active) {
            const int y = wi*P + ii - PADH;
            if (y >= 0) {
                #pragma unroll
                for (int jj = 0; jj < P; jj++) {
                    const int x2 = wj*P + jj - PADH;
                    if (x2 >= 0)
                        Og[(b*3+c)*65536 + y*256 + x2] = outr[jj];
                }
            }
        }
    }
}

// 5x5 conv (9->3 channels) fused with the final elementwise gate
__global__ __launch_bounds__(128) void conv_final_kernel(
    const float* __restrict__ X, const float* __restrict__ CW,
    const float* __restrict__ CB, float* __restrict__ out)
{
    __shared__ float sx[9][20][37];
    __shared__ float sw[675];
    __shared__ float sb[3];
    const int b = blockIdx.z;
    const int x0 = blockIdx.x * 32, y0 = blockIdx.y * 16;
    const int tid = threadIdx.x;

    for (int i2 = tid; i2 < 675; i2 += 128) sw[i2] = CW[i2];
    if (tid < 3) sb[tid] = CB[tid];
    for (int i2 = tid; i2 < 9*20*36; i2 += 128) {
        int ci = i2 / 720, rem = i2 % 720, yy = rem / 36, xx = rem % 36;
        int gy = y0 + yy - 2, gx = x0 + xx - 2;
        float v = 0.f;
        if ((unsigned)gy < 256u && (unsigned)gx < 256u) {
            const float* src = (ci < 3) ? g_x9 : ((ci < 6) ? g_x6 : g_x3);
            v = src[(b*3 + (ci % 3))*65536 + gy*256 + gx];
        }
        sx[ci][yy][xx] = v;
    }
    __syncthreads();

    const int tx = tid & 15, ty = tid >> 4;
    const int lx = tx*2, ly = ty*2;
    float acc[3][4];
    #pragma unroll
    for (int c2 = 0; c2 < 3; c2++)
        #pragma unroll
        for (int p2 = 0; p2 < 4; p2++) acc[c2][p2] = 0.f;

    #pragma unroll 1
    for (int ci = 0; ci < 9; ci++) {
        #pragma unroll
        for (int ky = 0; ky < 5; ky++) {
            #pragma unroll
            for (int kx = 0; kx < 5; kx++) {
                float w0 = sw[      ci*25 + ky*5 + kx];
                float w1 = sw[225 + ci*25 + ky*5 + kx];
                float w2 = sw[450 + ci*25 + ky*5 + kx];
                float a00 = sx[ci][ly+ky  ][lx+kx  ];
                float a01 = sx[ci][ly+ky  ][lx+kx+1];
                float a10 = sx[ci][ly+ky+1][lx+kx  ];
                float a11 = sx[ci][ly+ky+1][lx+kx+1];
                acc[0][0] += w0*a00; acc[0][1] += w0*a01; acc[0][2] += w0*a10; acc[0][3] += w0*a11;
                acc[1][0] += w1*a00; acc[1][1] += w1*a01; acc[1][2] += w1*a10; acc[1][3] += w1*a11;
                acc[2][0] += w2*a00; acc[2][1] += w2*a01; acc[2][2] += w2*a10; acc[2][3] += w2*a11;
            }
        }
    }

    const float xg = g_xg[b];
    #pragma unroll
    for (int co = 0; co < 3; co++) {
        #pragma unroll
        for (int py = 0; py < 2; py++) {
            #pragma unroll
            for (int px = 0; px < 2; px++) {
                int gy = y0 + ly + py, gx = x0 + lx + px;
                float x0v = fmaxf(acc[co][py*2+px] + sb[co], 0.f);
                float xv = X[(b*3+co)*65536 + gy*256 + gx];
                float r = fmaxf(xv * x0v + xg - x0v, 0.f);
                out[(b*3+co)*65536 + gy*256 + gx] = r;
            }
        }
    }
}

extern "C" void kernel_launch(void* const* d_in, const int* in_sizes, int n_in,
                              void* d_out, int out_size) {
    (void)in_sizes; (void)n_in; (void)out_size;
    const float* x   = (const float*)d_in[0];
    const float* w3  = (const float*)d_in[1];
    const float* b3  = (const float*)d_in[2];
    const float* hw3 = (const float*)d_in[3];
    const float* w6  = (const float*)d_in[4];
    const float* b6  = (const float*)d_in[5];
    const float* hw6 = (const float*)d_in[6];
    const float* w9  = (const float*)d_in[7];
    const float* b9  = (const float*)d_in[8];
    const float* hw9 = (const float*)d_in[9];
    const float* cw  = (const float*)d_in[10];
    const float* cb  = (const float*)d_in[11];
    float* out = (float*)d_out;

    max_kernel<<<4, 256>>>(x);
    attn1_kernel<<<1024, 256>>>(x, w3, b3, hw3);

    // stage 2: P=2, NH=4, WPB=16 -> 192 threads, 65536 windows
    attn_kernel<2, 4, 16><<<(65536 + 15) / 16, 16 * 12>>>(w6, b6, hw6);

    // stage 3: P=3, NH=2, WPB=16 -> 96 threads, 29584 windows
    attn_kernel<3, 2, 16><<<(29584 + 15) / 16, 16 * 6>>>(w9, b9, hw9);

    conv_final_kernel<<<dim3(8, 16, 4), 128>>>(x, cw, cb, out);
}